// round 7
// baseline (speedup 1.0000x reference)
#include <cuda_runtime.h>
#include <cstdint>
#include <cstddef>

#define BATCH 2
#define NN    1000
#define EE    2000
#define HH    128
#define BE    (BATCH*EE)   // 4000
#define BN    (BATCH*NN)   // 2000
#define SPLITK 4

__device__ float g_Z[4096*HH];              // padded; tail rows stay zero
__device__ float g_Ypart[SPLITK][4096*HH];  // padded split-K partials
__device__ float g_Y[BE*HH];
__device__ float g_Tp[HH*HH*HH];            // T tf32, pair-permuted (8 MB)

__device__ __forceinline__ uint32_t f2tf(float x) {
    uint32_t r; asm("cvt.rna.tf32.f32 %0, %1;" : "=r"(r) : "f"(x)); return r;
}
__device__ __forceinline__ float f2tff(float x) { return __uint_as_float(f2tf(x)); }

__device__ __forceinline__ void mma8(float c[4],
    uint32_t a0, uint32_t a1, uint32_t a2, uint32_t a3, uint32_t b0, uint32_t b1) {
    asm volatile(
        "mma.sync.aligned.m16n8k8.row.col.f32.tf32.tf32.f32 "
        "{%0,%1,%2,%3}, {%4,%5,%6,%7}, {%8,%9}, {%0,%1,%2,%3};\n"
        : "+f"(c[0]), "+f"(c[1]), "+f"(c[2]), "+f"(c[3])
        : "r"(a0), "r"(a1), "r"(a2), "r"(a3), "r"(b0), "r"(b1));
}
__device__ __forceinline__ void cp16(float* smem_dst, const float* gsrc) {
    uint32_t s = (uint32_t)__cvta_generic_to_shared(smem_dst);
    asm volatile("cp.async.cg.shared.global [%0], [%1], 16;\n" :: "r"(s), "l"(gsrc));
}
__device__ __forceinline__ void cp_commit() { asm volatile("cp.async.commit_group;\n"); }
__device__ __forceinline__ void cp_wait2()  { asm volatile("cp.async.wait_group 2;\n"); }

// ---------------------------------------------------------------------------
// convert: g_Tp = tf32(T), j-permuted inside each 8-group so (j, j+4) adjacent.
// ---------------------------------------------------------------------------
__global__ void convert_T_kernel(const float* __restrict__ en) {
    int i = blockIdx.x * 256 + threadIdx.x;     // float4 index
    float4 v = ((const float4*)en)[i];
    int base = i * 4;
    int row = base >> 7;
    int j   = base & 127;
    float* dst = g_Tp + ((size_t)row << 7) + (j & ~7);
    if ((j & 4) == 0) {
        dst[0] = f2tff(v.x); dst[2] = f2tff(v.y); dst[4] = f2tff(v.z); dst[6] = f2tff(v.w);
    } else {
        dst[1] = f2tff(v.x); dst[3] = f2tff(v.y); dst[5] = f2tff(v.z); dst[7] = f2tff(v.w);
    }
}

// ---------------------------------------------------------------------------
// Kernel 1: Z = node2edge @ node_state. Tile 32(e) x 128(h), grid (63,2)=126.
// ---------------------------------------------------------------------------
__global__ __launch_bounds__(256, 2)
void gemm1_kernel(const float* __restrict__ n2e, const float* __restrict__ ns) {
    __shared__ float As[32][36];
    __shared__ float Bs[32][136];
    const int tid = threadIdx.x, lane = tid & 31, warp = tid >> 5;
    const int gid = lane >> 2, tig = lane & 3;
    const int wcol = warp * 16;
    const int b = blockIdx.y, e0 = blockIdx.x * 32;
    const int rows = min(32, EE - e0);
    const float* Ag = n2e + (size_t)b * EE * NN;
    const float* Bg = ns  + (size_t)b * NN * HH;
    float acc[2][2][4] = {};
    const int NC = (NN + 31) / 32;

    float4 ar, br[4];
    auto ldA = [&](int c) {
        int k0 = c * 32, kv = NN - k0;
        int r = tid >> 3, c4 = (tid & 7) * 4;
        ar = make_float4(0.f,0.f,0.f,0.f);
        if (r < rows && c4 < kv) ar = *(const float4*)(Ag + (size_t)(e0 + r) * NN + k0 + c4);
    };
    auto ldB = [&](int c) {
        int k0 = c * 32, kv = NN - k0;
        #pragma unroll
        for (int i = 0; i < 4; i++) {
            int lin = tid + i * 256, kk = lin >> 5, c4 = (lin & 31) * 4;
            br[i] = make_float4(0.f,0.f,0.f,0.f);
            if (kk < kv) br[i] = *(const float4*)(Bg + (size_t)(k0 + kk) * HH + c4);
        }
    };
    ldA(0); ldB(0);

    for (int c = 0; c < NC; c++) {
        __syncthreads();
        { int r = tid >> 3, c4 = (tid & 7) * 4;
          As[r][c4+0]=f2tff(ar.x); As[r][c4+1]=f2tff(ar.y);
          As[r][c4+2]=f2tff(ar.z); As[r][c4+3]=f2tff(ar.w); }
        #pragma unroll
        for (int i = 0; i < 4; i++) {
            int lin = tid + i * 256, kk = lin >> 5, c4 = (lin & 31) * 4;
            Bs[kk][c4+0]=f2tff(br[i].x); Bs[kk][c4+1]=f2tff(br[i].y);
            Bs[kk][c4+2]=f2tff(br[i].z); Bs[kk][c4+3]=f2tff(br[i].w);
        }
        __syncthreads();
        if (c + 1 < NC) { ldA(c + 1); ldB(c + 1); }
        #pragma unroll
        for (int ks = 0; ks < 4; ks++) {
            const int kb = ks * 8;
            uint32_t a[2][4];
            #pragma unroll
            for (int mt = 0; mt < 2; mt++) {
                int r0 = mt * 16 + gid;
                a[mt][0] = __float_as_uint(As[r0    ][kb+tig  ]);
                a[mt][1] = __float_as_uint(As[r0 + 8][kb+tig  ]);
                a[mt][2] = __float_as_uint(As[r0    ][kb+tig+4]);
                a[mt][3] = __float_as_uint(As[r0 + 8][kb+tig+4]);
            }
            #pragma unroll
            for (int nt = 0; nt < 2; nt++) {
                int colb = wcol + nt * 8 + gid;
                uint32_t b0 = __float_as_uint(Bs[kb+tig  ][colb]);
                uint32_t b1 = __float_as_uint(Bs[kb+tig+4][colb]);
                mma8(acc[0][nt], a[0][0],a[0][1],a[0][2],a[0][3], b0,b1);
                mma8(acc[1][nt], a[1][0],a[1][1],a[1][2],a[1][3], b0,b1);
            }
        }
    }
    #pragma unroll
    for (int mt = 0; mt < 2; mt++)
        #pragma unroll
        for (int nt = 0; nt < 2; nt++) {
            int col = wcol + nt * 8 + tig * 2;
            int r0 = mt * 16 + gid, r1 = r0 + 8;
            if (r0 < rows) { float* p = g_Z + ((size_t)(b*EE + e0 + r0))*HH + col; p[0]=acc[mt][nt][0]; p[1]=acc[mt][nt][1]; }
            if (r1 < rows) { float* p = g_Z + ((size_t)(b*EE + e0 + r1))*HH + col; p[0]=acc[mt][nt][2]; p[1]=acc[mt][nt][3]; }
        }
}

// ---------------------------------------------------------------------------
// Main kernel: Y[r,i] = sum_{h,j} X[r,h]*T[h,i,j]*Z[r,j].
// 512 threads, tile 128 rows x 128 i; split-K over h (4 x 32).
// grid (32,4) = 128 CTAs = one wave, 16 warps/SM.
// 16 warps = 4(M) x 4(N), warp tile 32 x 32.
// 4-stage cp.async pipeline on T chunks; B frags via LDS.64 (permuted T).
// ---------------------------------------------------------------------------
#define XS_E (128*36)
#define TBS  (128*40)
#define MAIN_SMEM ((XS_E + 4*TBS) * 4)   // 100352 B

__global__ __launch_bounds__(512, 1)
void gemm_main_kernel(const float* __restrict__ ev) {
    extern __shared__ float sm[];
    float* Xs = sm;               // [128][36] raw fp32 (32 h-cols)
    float* Tb = sm + XS_E;        // 4 x [128][40] tf32 bits (pair-permuted)

    const int tid = threadIdx.x, lane = tid & 31, warp = tid >> 5;
    const int gid = lane >> 2, tig = lane & 3;
    const int wrow = (warp & 3) * 32, wcol = (warp >> 2) * 32;
    const int row0 = blockIdx.x * 128;
    const int rows = min(128, BE - row0);
    const int h0 = blockIdx.y * 32;

    auto issueT = [&](int c) {
        const int hn = c & 31, j0n = (c >> 5) * 32;
        const float* src = g_Tp + (size_t)(h0 + hn) * (HH*HH) + j0n;
        float* dst = Tb + (c & 3) * TBS;
        #pragma unroll
        for (int i = 0; i < 2; i++) {
            int lin = tid + i * 512, ir = lin >> 3, c4 = (lin & 7) * 4;
            cp16(dst + ir*40 + c4, src + (size_t)ir*HH + c4);
        }
    };
    issueT(0); cp_commit();
    issueT(1); cp_commit();
    issueT(2); cp_commit();

    // Xs: rows x 32 h-cols, raw fp32
    #pragma unroll
    for (int i = 0; i < 2; i++) {
        int lin = tid + i * 512, r = lin >> 3, c4 = (lin & 7) * 4;
        float4 v = make_float4(0.f,0.f,0.f,0.f);
        if (r < rows) v = *(const float4*)(ev + (size_t)(row0 + r) * HH + h0 + c4);
        Xs[r*36+c4+0]=v.x; Xs[r*36+c4+1]=v.y; Xs[r*36+c4+2]=v.z; Xs[r*36+c4+3]=v.w;
    }
    __syncthreads();

    const int R0 = wrow + gid;
    float acc[2][4][4] = {};

    for (int j0i = 0; j0i < 4; j0i++) {
        const int j0 = j0i * 32;
        // Z fragments straight from GMEM (padded g_Z -> no guard needed)
        float zr[4][8];
        #pragma unroll
        for (int r = 0; r < 4; r++) {
            const float* zp = g_Z + (size_t)(row0 + R0 + 8*r) * HH + j0 + tig;
            #pragma unroll
            for (int q = 0; q < 8; q++) zr[r][q] = zp[4*q];
        }

        #pragma unroll 1
        for (int hi = 0; hi < 32; hi++) {
            const int cc = j0i * 32 + hi;
            cp_wait2();
            __syncthreads();
            if (cc + 3 < 128) issueT(cc + 3);
            cp_commit();

            const float* Bsb = Tb + (cc & 3) * TBS;
            float xv0 = Xs[ R0      *36 + hi];
            float xv1 = Xs[(R0 +  8)*36 + hi];
            float xv2 = Xs[(R0 + 16)*36 + hi];
            float xv3 = Xs[(R0 + 24)*36 + hi];

            #pragma unroll
            for (int ks = 0; ks < 4; ks++) {
                const int kb = ks * 8;
                uint32_t a00 = f2tf(xv0 * zr[0][2*ks  ]);
                uint32_t a01 = f2tf(xv1 * zr[1][2*ks  ]);
                uint32_t a02 = f2tf(xv0 * zr[0][2*ks+1]);
                uint32_t a03 = f2tf(xv1 * zr[1][2*ks+1]);
                uint32_t a10 = f2tf(xv2 * zr[2][2*ks  ]);
                uint32_t a11 = f2tf(xv3 * zr[3][2*ks  ]);
                uint32_t a12 = f2tf(xv2 * zr[2][2*ks+1]);
                uint32_t a13 = f2tf(xv3 * zr[3][2*ks+1]);
                #pragma unroll
                for (int nt = 0; nt < 4; nt++) {
                    int colb = wcol + nt * 8 + gid;
                    float2 bv = *(const float2*)(Bsb + colb*40 + kb + 2*tig);
                    uint32_t b0 = __float_as_uint(bv.x);
                    uint32_t b1 = __float_as_uint(bv.y);
                    mma8(acc[0][nt], a00,a01,a02,a03, b0,b1);
                    mma8(acc[1][nt], a10,a11,a12,a13, b0,b1);
                }
            }
        }
    }

    // padded g_Ypart -> no row guard
    float* Yp = g_Ypart[blockIdx.y];
    #pragma unroll
    for (int mt = 0; mt < 2; mt++)
        #pragma unroll
        for (int nt = 0; nt < 4; nt++) {
            int col = wcol + nt * 8 + tig * 2;
            int r0 = wrow + mt * 16 + gid, r1 = r0 + 8;
            { float* p = Yp + (size_t)(row0+r0)*HH + col; p[0]=acc[mt][nt][0]; p[1]=acc[mt][nt][1]; }
            { float* p = Yp + (size_t)(row0+r1)*HH + col; p[0]=acc[mt][nt][2]; p[1]=acc[mt][nt][3]; }
        }
}

// ---------------------------------------------------------------------------
__global__ void reduce_kernel() {
    int i0 = (blockIdx.x * 256 + threadIdx.x) * 8;
    #pragma unroll
    for (int half = 0; half < 2; half++) {
        int idx = i0 + half * 4;
        float4 a = *(const float4*)&g_Ypart[0][idx];
        float4 b = *(const float4*)&g_Ypart[1][idx];
        float4 c = *(const float4*)&g_Ypart[2][idx];
        float4 d = *(const float4*)&g_Ypart[3][idx];
        *(float4*)&g_Y[idx] = make_float4(a.x+b.x+c.x+d.x, a.y+b.y+c.y+d.y,
                                          a.z+b.z+c.z+d.z, a.w+b.w+c.w+d.w);
    }
}

// ---------------------------------------------------------------------------
// Kernel 3: out = (edge2node @ Y + node_state) / (1 + rowsum(edge2node)).
// Tile 16 x 128, norm fused into A loads. grid (63, 2).
// ---------------------------------------------------------------------------
__global__ __launch_bounds__(256, 2)
void gemm3_kernel(const float* __restrict__ e2n, const float* __restrict__ ns,
                  float* __restrict__ out) {
    __shared__ float As[16][36];
    __shared__ float Bs[32][136];
    __shared__ float nsp[128];
    __shared__ float nv_s[16];
    const int tid = threadIdx.x, lane = tid & 31, warp = tid >> 5;
    const int gid = lane >> 2, tig = lane & 3;
    const int wcol = warp * 16;
    const int b = blockIdx.y, n0 = blockIdx.x * 16;
    const int rows = min(16, NN - n0);
    const float* Ag = e2n + ((size_t)b * NN + n0) * EE;
    const float* Bg = g_Y + (size_t)b * EE * HH;
    float acc[2][4] = {};
    float asum = 0.f;
    const int NC = (EE + 31) / 32;

    float4 ar, br[4];
    auto ldA = [&](int c) {
        int k0 = c * 32, kv = EE - k0;
        int r = tid >> 3, c4 = (tid & 7) * 4;
        ar = make_float4(0.f,0.f,0.f,0.f);
        if (r < rows && c4 < kv && tid < 128)
            ar = *(const float4*)(Ag + (size_t)r * EE + k0 + c4);
        asum += ar.x + ar.y + ar.z + ar.w;
    };
    auto ldB = [&](int c) {
        int k0 = c * 32, kv = EE - k0;
        #pragma unroll
        for (int i = 0; i < 4; i++) {
            int lin = tid + i * 256, kk = lin >> 5, c4 = (lin & 31) * 4;
            br[i] = make_float4(0.f,0.f,0.f,0.f);
            if (kk < kv) br[i] = *(const float4*)(Bg + (size_t)(k0 + kk) * HH + c4);
        }
    };
    ldA(0); ldB(0);

    for (int c = 0; c < NC; c++) {
        __syncthreads();
        if (tid < 128) {
            int r = tid >> 3, c4 = (tid & 7) * 4;
            As[r][c4+0]=f2tff(ar.x); As[r][c4+1]=f2tff(ar.y);
            As[r][c4+2]=f2tff(ar.z); As[r][c4+3]=f2tff(ar.w);
        }
        #pragma unroll
        for (int i = 0; i < 4; i++) {
            int lin = tid + i * 256, kk = lin >> 5, c4 = (lin & 31) * 4;
            Bs[kk][c4+0]=f2tff(br[i].x); Bs[kk][c4+1]=f2tff(br[i].y);
            Bs[kk][c4+2]=f2tff(br[i].z); Bs[kk][c4+3]=f2tff(br[i].w);
        }
        __syncthreads();
        if (c + 1 < NC) { ldA(c + 1); ldB(c + 1); }
        #pragma unroll
        for (int ks = 0; ks < 4; ks++) {
            const int kb = ks * 8;
            uint32_t a0 = __float_as_uint(As[gid    ][kb+tig  ]);
            uint32_t a1 = __float_as_uint(As[gid + 8][kb+tig  ]);
            uint32_t a2 = __float_as_uint(As[gid    ][kb+tig+4]);
            uint32_t a3 = __float_as_uint(As[gid + 8][kb+tig+4]);
            #pragma unroll
            for (int nt = 0; nt < 2; nt++) {
                int colb = wcol + nt * 8 + gid;
                uint32_t b0 = __float_as_uint(Bs[kb+tig  ][colb]);
                uint32_t b1 = __float_as_uint(Bs[kb+tig+4][colb]);
                mma8(acc[nt], a0, a1, a2, a3, b0, b1);
            }
        }
    }
    if (tid < 128) nsp[tid] = asum;
    __syncthreads();
    if (tid < 16) {
        float s = 1.f;
        #pragma unroll
        for (int k = 0; k < 8; k++) s += nsp[tid*8 + k];
        nv_s[tid] = s;
    }
    __syncthreads();

    const float* nsb = ns + ((size_t)b * NN) * HH;
    #pragma unroll
    for (int nt = 0; nt < 2; nt++) {
        int col = wcol + nt * 8 + tig * 2;
        int r0 = gid, r1 = gid + 8;
        if (r0 < rows) {
            size_t idx = (size_t)(n0 + r0) * HH + col;
            float nv = nv_s[r0];
            float* po = out + (size_t)b * NN * HH + idx;
            po[0] = (acc[nt][0] + nsb[idx  ]) / nv;
            po[1] = (acc[nt][1] + nsb[idx+1]) / nv;
        }
        if (r1 < rows) {
            size_t idx = (size_t)(n0 + r1) * HH + col;
            float nv = nv_s[r1];
            float* po = out + (size_t)b * NN * HH + idx;
            po[0] = (acc[nt][2] + nsb[idx  ]) / nv;
            po[1] = (acc[nt][3] + nsb[idx+1]) / nv;
        }
    }
}

// ---------------------------------------------------------------------------
extern "C" void kernel_launch(void* const* d_in, const int* in_sizes, int n_in,
                              void* d_out, int out_size) {
    const float* node_state = (const float*)d_in[0];
    const float* edge_vec   = (const float*)d_in[1];
    const float* node2edge  = (const float*)d_in[2];
    const float* edge2node  = (const float*)d_in[3];
    const float* edge_net   = (const float*)d_in[4];
    float* out = (float*)d_out;

    cudaFuncSetAttribute(gemm_main_kernel,
                         cudaFuncAttributeMaxDynamicSharedMemorySize, MAIN_SMEM);

    convert_T_kernel<<<(HH*HH*HH)/4/256, 256>>>(edge_net);
    gemm1_kernel<<<dim3(63, 2), 256>>>(node2edge, node_state);
    gemm_main_kernel<<<dim3(32, SPLITK), 512, MAIN_SMEM>>>(edge_vec);
    reduce_kernel<<<250, 256>>>();
    gemm3_kernel<<<dim3(63, 2), 256>>>(edge2node, node_state, out);
}

// round 9
// speedup vs baseline: 1.2535x; 1.2535x over previous
#include <cuda_runtime.h>
#include <cstdint>
#include <cstddef>

#define BATCH 2
#define NN    1000
#define EE    2000
#define HH    128
#define BE    (BATCH*EE)   // 4000
#define BN    (BATCH*NN)   // 2000
#define SPLITK 4

__device__ float g_Z[4096*HH];              // padded; tail rows stay zero
__device__ float g_Ypart[SPLITK][4096*HH];  // padded split-K partials
__device__ float g_Y[BE*HH];
__device__ unsigned short g_T16[HH*HH*HH];  // T fp16, pair-permuted j (4 MB)

__device__ __forceinline__ uint32_t f2tf(float x) {
    uint32_t r; asm("cvt.rna.tf32.f32 %0, %1;" : "=r"(r) : "f"(x)); return r;
}
__device__ __forceinline__ float f2tff(float x) { return __uint_as_float(f2tf(x)); }

__device__ __forceinline__ void mma8(float c[4],
    uint32_t a0, uint32_t a1, uint32_t a2, uint32_t a3, uint32_t b0, uint32_t b1) {
    asm volatile(
        "mma.sync.aligned.m16n8k8.row.col.f32.tf32.tf32.f32 "
        "{%0,%1,%2,%3}, {%4,%5,%6,%7}, {%8,%9}, {%0,%1,%2,%3};\n"
        : "+f"(c[0]), "+f"(c[1]), "+f"(c[2]), "+f"(c[3])
        : "r"(a0), "r"(a1), "r"(a2), "r"(a3), "r"(b0), "r"(b1));
}
__device__ __forceinline__ void mma16(float c[4],
    uint32_t a0, uint32_t a1, uint32_t a2, uint32_t a3, uint32_t b0, uint32_t b1) {
    asm volatile(
        "mma.sync.aligned.m16n8k16.row.col.f32.f16.f16.f32 "
        "{%0,%1,%2,%3}, {%4,%5,%6,%7}, {%8,%9}, {%0,%1,%2,%3};\n"
        : "+f"(c[0]), "+f"(c[1]), "+f"(c[2]), "+f"(c[3])
        : "r"(a0), "r"(a1), "r"(a2), "r"(a3), "r"(b0), "r"(b1));
}
__device__ __forceinline__ void cp_commit() { asm volatile("cp.async.commit_group;\n"); }

// ---------------------------------------------------------------------------
// convert: g_T16 = fp16(T), j pair-permuted within each 16-group:
// local pair t -> position 2t, pair t+4 -> position 2t+1 (pairs t,t+4 adjacent).
// ---------------------------------------------------------------------------
__global__ void convert_T16(const float* __restrict__ en) {
    int idx = blockIdx.x * 256 + threadIdx.x;    // pair index, 2^20 total
    float2 v = ((const float2*)en)[idx];
    int p = idx & 63;
    int rowhi = idx >> 6;                        // h*128 + i
    int pl = p & 7, g = p >> 3;
    int pos = g*8 + 2*(pl&3) + (pl>>2);
    uint32_t d;
    asm("cvt.rn.f16x2.f32 %0, %1, %2;" : "=r"(d) : "f"(v.y), "f"(v.x));
    *(uint32_t*)(g_T16 + (size_t)rowhi*128 + pos*2) = d;
}

// ---------------------------------------------------------------------------
// Kernel 1: Z = node2edge @ node_state (tf32). Tile 32 x 128, grid (63,2).
// ---------------------------------------------------------------------------
__global__ __launch_bounds__(256, 2)
void gemm1_kernel(const float* __restrict__ n2e, const float* __restrict__ ns) {
    __shared__ float As[32][36];
    __shared__ float Bs[32][136];
    const int tid = threadIdx.x, lane = tid & 31, warp = tid >> 5;
    const int gid = lane >> 2, tig = lane & 3;
    const int wcol = warp * 16;
    const int b = blockIdx.y, e0 = blockIdx.x * 32;
    const int rows = min(32, EE - e0);
    const float* Ag = n2e + (size_t)b * EE * NN;
    const float* Bg = ns  + (size_t)b * NN * HH;
    float acc[2][2][4] = {};
    const int NC = (NN + 31) / 32;

    float4 ar, br[4];
    auto ldA = [&](int c) {
        int k0 = c * 32, kv = NN - k0;
        int r = tid >> 3, c4 = (tid & 7) * 4;
        ar = make_float4(0.f,0.f,0.f,0.f);
        if (r < rows && c4 < kv) ar = *(const float4*)(Ag + (size_t)(e0 + r) * NN + k0 + c4);
    };
    auto ldB = [&](int c) {
        int k0 = c * 32, kv = NN - k0;
        #pragma unroll
        for (int i = 0; i < 4; i++) {
            int lin = tid + i * 256, kk = lin >> 5, c4 = (lin & 31) * 4;
            br[i] = make_float4(0.f,0.f,0.f,0.f);
            if (kk < kv) br[i] = *(const float4*)(Bg + (size_t)(k0 + kk) * HH + c4);
        }
    };
    ldA(0); ldB(0);

    for (int c = 0; c < NC; c++) {
        __syncthreads();
        { int r = tid >> 3, c4 = (tid & 7) * 4;
          As[r][c4+0]=f2tff(ar.x); As[r][c4+1]=f2tff(ar.y);
          As[r][c4+2]=f2tff(ar.z); As[r][c4+3]=f2tff(ar.w); }
        #pragma unroll
        for (int i = 0; i < 4; i++) {
            int lin = tid + i * 256, kk = lin >> 5, c4 = (lin & 31) * 4;
            Bs[kk][c4+0]=f2tff(br[i].x); Bs[kk][c4+1]=f2tff(br[i].y);
            Bs[kk][c4+2]=f2tff(br[i].z); Bs[kk][c4+3]=f2tff(br[i].w);
        }
        __syncthreads();
        if (c + 1 < NC) { ldA(c + 1); ldB(c + 1); }
        #pragma unroll
        for (int ks = 0; ks < 4; ks++) {
            const int kb = ks * 8;
            uint32_t a[2][4];
            #pragma unroll
            for (int mt = 0; mt < 2; mt++) {
                int r0 = mt * 16 + gid;
                a[mt][0] = __float_as_uint(As[r0    ][kb+tig  ]);
                a[mt][1] = __float_as_uint(As[r0 + 8][kb+tig  ]);
                a[mt][2] = __float_as_uint(As[r0    ][kb+tig+4]);
                a[mt][3] = __float_as_uint(As[r0 + 8][kb+tig+4]);
            }
            #pragma unroll
            for (int nt = 0; nt < 2; nt++) {
                int colb = wcol + nt * 8 + gid;
                uint32_t b0 = __float_as_uint(Bs[kb+tig  ][colb]);
                uint32_t b1 = __float_as_uint(Bs[kb+tig+4][colb]);
                mma8(acc[0][nt], a[0][0],a[0][1],a[0][2],a[0][3], b0,b1);
                mma8(acc[1][nt], a[1][0],a[1][1],a[1][2],a[1][3], b0,b1);
            }
        }
    }
    #pragma unroll
    for (int mt = 0; mt < 2; mt++)
        #pragma unroll
        for (int nt = 0; nt < 2; nt++) {
            int col = wcol + nt * 8 + tig * 2;
            int r0 = mt * 16 + gid, r1 = r0 + 8;
            if (r0 < rows) { float* p = g_Z + ((size_t)(b*EE + e0 + r0))*HH + col; p[0]=acc[mt][nt][0]; p[1]=acc[mt][nt][1]; }
            if (r1 < rows) { float* p = g_Z + ((size_t)(b*EE + e0 + r1))*HH + col; p[0]=acc[mt][nt][2]; p[1]=acc[mt][nt][3]; }
        }
}

// ---------------------------------------------------------------------------
// MAIN (fp16 m16n8k16): Y[r,i] = sum_{h,j} X[r,h]*T[h,i,j]*Z[r,j].
// 512 thr, tile 128 r x 128 i; split-K over h (4 x 32); grid (32,4)=128 CTAs.
// A (=x*z, fp16) staged in SMEM (built once per CTA, double-buffered);
// B (=T fp16, pair-permuted) 4-deep cp.async pipeline. All frags via
// VOLATILE LDS.64 (ordering vs bar.sync/STS/cp.async is load-bearing).
// ---------------------------------------------------------------------------
#define TB_BYTES (128*96)                  // one T chunk buffer
#define PB_OFF   (4*TB_BYTES)              // 49152
#define PB_BYTES (128*96)
#define XS_OFF   (PB_OFF + 2*PB_BYTES)     // 73728
#define MAIN_SMEM (XS_OFF + 128*36*4)      // 92160 B

__global__ __launch_bounds__(512, 1)
void gemm_main_kernel(const float* __restrict__ ev) {
    extern __shared__ char smc[];
    uint32_t sb;
    asm("{ .reg .u64 t; cvta.to.shared.u64 t, %1; cvt.u32.u64 %0, t; }" : "=r"(sb) : "l"((void*)smc));
    float* Xs = (float*)(smc + XS_OFF);
    const int tid = threadIdx.x, lane = tid & 31, warp = tid >> 5;
    const int gid = lane >> 2, tig = lane & 3;
    const int wrow = (warp & 3) * 32, wcol = (warp >> 2) * 32;
    const int row0 = blockIdx.x * 128;
    const int h0 = blockIdx.y * 32;

    // T chunk cp.async: 128 rows x 64B, one 16B per thread
    const int ti_row = tid >> 2, ti_seg = tid & 3;
    auto issueT = [&](int c) {
        const int hn = c & 31, j0n = (c >> 5) * 32;
        const unsigned short* src =
            g_T16 + ((size_t)((h0 + hn) * 128 + ti_row)) * 128 + j0n + ti_seg * 8;
        uint32_t dst = sb + (uint32_t)(c & 3) * TB_BYTES + ti_row * 96 + ti_seg * 16;
        asm volatile("cp.async.cg.shared.global [%0], [%1], 16;\n" :: "r"(dst), "l"(src));
    };
    issueT(0); cp_commit();
    issueT(1); cp_commit();
    issueT(2); cp_commit();

    // Xs[r][h] fp32, stride 36 (guarded: rows >= BE -> 0)
    #pragma unroll
    for (int i = 0; i < 2; i++) {
        int lin = tid + i * 512, r = lin >> 3, c4 = (lin & 7) * 4;
        float4 v = make_float4(0.f,0.f,0.f,0.f);
        if (row0 + r < BE) v = *(const float4*)(ev + (size_t)(row0 + r) * HH + h0 + c4);
        Xs[r*36+c4]=v.x; Xs[r*36+c4+1]=v.y; Xs[r*36+c4+2]=v.z; Xs[r*36+c4+3]=v.w;
    }

    // builder: thread -> (row, quarter); writes 4 fp16x2 pairs (permuted) = STS.128
    const int brow = tid >> 2, bq = tid & 3;
    const uint32_t bdst = sb + PB_OFF + brow * 96 + bq * 16;
    const float* zrow = g_Z + (size_t)(row0 + brow) * HH;
    float zv[8];
    auto loadz = [&](int j0b) {
        int b1 = j0b + (bq & 1) * 4 + (bq >> 1) * 16;
        float4 u = *(const float4*)(zrow + b1);
        float4 w = *(const float4*)(zrow + b1 + 8);
        zv[0]=u.x; zv[1]=u.y; zv[2]=u.z; zv[3]=u.w;
        zv[4]=w.x; zv[5]=w.y; zv[6]=w.z; zv[7]=w.w;
    };
    auto buildP = [&](int nc) {
        float x = Xs[brow*36 + (nc & 31)];
        uint32_t r0,r1,r2,r3;
        asm("cvt.rn.f16x2.f32 %0, %1, %2;" : "=r"(r0) : "f"(x*zv[1]), "f"(x*zv[0]));
        asm("cvt.rn.f16x2.f32 %0, %1, %2;" : "=r"(r1) : "f"(x*zv[5]), "f"(x*zv[4]));
        asm("cvt.rn.f16x2.f32 %0, %1, %2;" : "=r"(r2) : "f"(x*zv[3]), "f"(x*zv[2]));
        asm("cvt.rn.f16x2.f32 %0, %1, %2;" : "=r"(r3) : "f"(x*zv[7]), "f"(x*zv[6]));
        uint32_t d = bdst + (uint32_t)(nc & 1) * PB_BYTES;
        asm volatile("st.shared.v4.b32 [%0], {%1,%2,%3,%4};"
                     :: "r"(d), "r"(r0), "r"(r1), "r"(r2), "r"(r3));
    };
    loadz(0);
    __syncthreads();     // Xs visible
    buildP(0);

    float acc[2][4][4] = {};

    for (int cc = 0; cc < 128; cc++) {
        asm volatile("cp.async.wait_group 2;\n" ::: "memory");
        __syncthreads();                 // P(cc) + T(cc) visible; prev reads done
        if (cc + 3 < 128) issueT(cc + 3);
        cp_commit();
        int nc = cc + 1;
        if (nc < 128) {
            if ((nc & 31) == 0) loadz((nc >> 5) * 32);
            buildP(nc);
        }
        uint32_t Pbuf = sb + PB_OFF + (uint32_t)(cc & 1) * PB_BYTES;
        uint32_t Tbuf = sb + (uint32_t)(cc & 3) * TB_BYTES;
        #pragma unroll
        for (int ks = 0; ks < 2; ks++) {
            uint32_t a0[2], a1[2], a2[2], a3[2];
            #pragma unroll
            for (int mt = 0; mt < 2; mt++) {
                uint32_t ra = Pbuf + (uint32_t)(wrow + mt*16 + gid) * 96 + ks*32 + tig*8;
                asm volatile("ld.shared.v2.b32 {%0,%1}, [%2];"
                             : "=r"(a0[mt]), "=r"(a2[mt]) : "r"(ra) : "memory");
                asm volatile("ld.shared.v2.b32 {%0,%1}, [%2];"
                             : "=r"(a1[mt]), "=r"(a3[mt]) : "r"(ra + 8*96) : "memory");
            }
            #pragma unroll
            for (int nt = 0; nt < 4; nt++) {
                uint32_t rb = Tbuf + (uint32_t)(wcol + nt*8 + gid) * 96 + ks*32 + tig*8;
                uint32_t b0, b1;
                asm volatile("ld.shared.v2.b32 {%0,%1}, [%2];"
                             : "=r"(b0), "=r"(b1) : "r"(rb) : "memory");
                mma16(acc[0][nt], a0[0],a1[0],a2[0],a3[0], b0,b1);
                mma16(acc[1][nt], a0[1],a1[1],a2[1],a3[1], b0,b1);
            }
        }
    }

    // padded g_Ypart -> no row guard
    float* Yp = g_Ypart[blockIdx.y];
    #pragma unroll
    for (int mt = 0; mt < 2; mt++)
        #pragma unroll
        for (int nt = 0; nt < 4; nt++) {
            int col = wcol + nt * 8 + tig * 2;
            int r0 = row0 + wrow + mt * 16 + gid;
            float* p0 = Yp + (size_t)r0 * HH + col;
            p0[0] = acc[mt][nt][0]; p0[1] = acc[mt][nt][1];
            float* p1 = Yp + (size_t)(r0 + 8) * HH + col;
            p1[0] = acc[mt][nt][2]; p1[1] = acc[mt][nt][3];
        }
}

// ---------------------------------------------------------------------------
__global__ void reduce_kernel() {
    int i0 = (blockIdx.x * 256 + threadIdx.x) * 8;
    #pragma unroll
    for (int half = 0; half < 2; half++) {
        int idx = i0 + half * 4;
        float4 a = *(const float4*)&g_Ypart[0][idx];
        float4 b = *(const float4*)&g_Ypart[1][idx];
        float4 c = *(const float4*)&g_Ypart[2][idx];
        float4 d = *(const float4*)&g_Ypart[3][idx];
        *(float4*)&g_Y[idx] = make_float4(a.x+b.x+c.x+d.x, a.y+b.y+c.y+d.y,
                                          a.z+b.z+c.z+d.z, a.w+b.w+c.w+d.w);
    }
}

// ---------------------------------------------------------------------------
// Kernel 3: out = (edge2node @ Y + node_state) / (1 + rowsum(edge2node)).
// Tile 16 x 128, norm fused into A loads. grid (63, 2).
// ---------------------------------------------------------------------------
__global__ __launch_bounds__(256, 2)
void gemm3_kernel(const float* __restrict__ e2n, const float* __restrict__ ns,
                  float* __restrict__ out) {
    __shared__ float As[16][36];
    __shared__ float Bs[32][136];
    __shared__ float nsp[128];
    __shared__ float nv_s[16];
    const int tid = threadIdx.x, lane = tid & 31, warp = tid >> 5;
    const int gid = lane >> 2, tig = lane & 3;
    const int wcol = warp * 16;
    const int b = blockIdx.y, n0 = blockIdx.x * 16;
    const int rows = min(16, NN - n0);
    const float* Ag = e2n + ((size_t)b * NN + n0) * EE;
    const float* Bg = g_Y + (size_t)b * EE * HH;
    float acc[2][4] = {};
    float asum = 0.f;
    const int NC = (EE + 31) / 32;

    float4 ar, br[4];
    auto ldA = [&](int c) {
        int k0 = c * 32, kv = EE - k0;
        int r = tid >> 3, c4 = (tid & 7) * 4;
        ar = make_float4(0.f,0.f,0.f,0.f);
        if (r < rows && c4 < kv && tid < 128)
            ar = *(const float4*)(Ag + (size_t)r * EE + k0 + c4);
        asum += ar.x + ar.y + ar.z + ar.w;
    };
    auto ldB = [&](int c) {
        int k0 = c * 32, kv = EE - k0;
        #pragma unroll
        for (int i = 0; i < 4; i++) {
            int lin = tid + i * 256, kk = lin >> 5, c4 = (lin & 31) * 4;
            br[i] = make_float4(0.f,0.f,0.f,0.f);
            if (kk < kv) br[i] = *(const float4*)(Bg + (size_t)(k0 + kk) * HH + c4);
        }
    };
    ldA(0); ldB(0);

    for (int c = 0; c < NC; c++) {
        __syncthreads();
        if (tid < 128) {
            int r = tid >> 3, c4 = (tid & 7) * 4;
            As[r][c4+0]=f2tff(ar.x); As[r][c4+1]=f2tff(ar.y);
            As[r][c4+2]=f2tff(ar.z); As[r][c4+3]=f2tff(ar.w);
        }
        #pragma unroll
        for (int i = 0; i < 4; i++) {
            int lin = tid + i * 256, kk = lin >> 5, c4 = (lin & 31) * 4;
            Bs[kk][c4+0]=f2tff(br[i].x); Bs[kk][c4+1]=f2tff(br[i].y);
            Bs[kk][c4+2]=f2tff(br[i].z); Bs[kk][c4+3]=f2tff(br[i].w);
        }
        __syncthreads();
        if (c + 1 < NC) { ldA(c + 1); ldB(c + 1); }
        #pragma unroll
        for (int ks = 0; ks < 4; ks++) {
            const int kb = ks * 8;
            uint32_t a0 = __float_as_uint(As[gid    ][kb+tig  ]);
            uint32_t a1 = __float_as_uint(As[gid + 8][kb+tig  ]);
            uint32_t a2 = __float_as_uint(As[gid    ][kb+tig+4]);
            uint32_t a3 = __float_as_uint(As[gid + 8][kb+tig+4]);
            #pragma unroll
            for (int nt = 0; nt < 2; nt++) {
                int colb = wcol + nt * 8 + gid;
                uint32_t b0 = __float_as_uint(Bs[kb+tig  ][colb]);
                uint32_t b1 = __float_as_uint(Bs[kb+tig+4][colb]);
                mma8(acc[nt], a0, a1, a2, a3, b0, b1);
            }
        }
    }
    if (tid < 128) nsp[tid] = asum;
    __syncthreads();
    if (tid < 16) {
        float s = 1.f;
        #pragma unroll
        for (int k = 0; k < 8; k++) s += nsp[tid*8 + k];
        nv_s[tid] = s;
    }
    __syncthreads();

    const float* nsb = ns + ((size_t)b * NN) * HH;
    #pragma unroll
    for (int nt = 0; nt < 2; nt++) {
        int col = wcol + nt * 8 + tig * 2;
        int r0 = gid, r1 = gid + 8;
        if (r0 < rows) {
            size_t idx = (size_t)(n0 + r0) * HH + col;
            float nv = nv_s[r0];
            float* po = out + (size_t)b * NN * HH + idx;
            po[0] = (acc[nt][0] + nsb[idx  ]) / nv;
            po[1] = (acc[nt][1] + nsb[idx+1]) / nv;
        }
        if (r1 < rows) {
            size_t idx = (size_t)(n0 + r1) * HH + col;
            float nv = nv_s[r1];
            float* po = out + (size_t)b * NN * HH + idx;
            po[0] = (acc[nt][2] + nsb[idx  ]) / nv;
            po[1] = (acc[nt][3] + nsb[idx+1]) / nv;
        }
    }
}

// ---------------------------------------------------------------------------
extern "C" void kernel_launch(void* const* d_in, const int* in_sizes, int n_in,
                              void* d_out, int out_size) {
    const float* node_state = (const float*)d_in[0];
    const float* edge_vec   = (const float*)d_in[1];
    const float* node2edge  = (const float*)d_in[2];
    const float* edge2node  = (const float*)d_in[3];
    const float* edge_net   = (const float*)d_in[4];
    float* out = (float*)d_out;

    cudaFuncSetAttribute(gemm_main_kernel,
                         cudaFuncAttributeMaxDynamicSharedMemorySize, MAIN_SMEM);

    convert_T16<<<4096, 256>>>(edge_net);
    gemm1_kernel<<<dim3(63, 2), 256>>>(node2edge, node_state);
    gemm_main_kernel<<<dim3(32, SPLITK), 512, MAIN_SMEM>>>(edge_vec);
    reduce_kernel<<<250, 256>>>();
    gemm3_kernel<<<dim3(63, 2), 256>>>(edge2node, node_state, out);
}

// round 10
// speedup vs baseline: 1.4651x; 1.1688x over previous
#include <cuda_runtime.h>
#include <cstdint>
#include <cstddef>

#define BATCH 2
#define NN    1000
#define EE    2000
#define HH    128
#define BE    (BATCH*EE)   // 4000
#define BN    (BATCH*NN)   // 2000
#define SPLITK 4

__device__ float g_Z[4096*HH];              // padded; tail rows stay zero
__device__ float g_Ypart[SPLITK][4096*HH];  // padded split-K partials
__device__ float g_Y[BE*HH];
__device__ unsigned short g_T16[HH*HH*HH];  // T fp16, pair-permuted j (4 MB)

__device__ __forceinline__ uint32_t f2tf(float x) {
    uint32_t r; asm("cvt.rna.tf32.f32 %0, %1;" : "=r"(r) : "f"(x)); return r;
}
__device__ __forceinline__ float f2tff(float x) { return __uint_as_float(f2tf(x)); }

__device__ __forceinline__ void mma8(float c[4],
    uint32_t a0, uint32_t a1, uint32_t a2, uint32_t a3, uint32_t b0, uint32_t b1) {
    asm volatile(
        "mma.sync.aligned.m16n8k8.row.col.f32.tf32.tf32.f32 "
        "{%0,%1,%2,%3}, {%4,%5,%6,%7}, {%8,%9}, {%0,%1,%2,%3};\n"
        : "+f"(c[0]), "+f"(c[1]), "+f"(c[2]), "+f"(c[3])
        : "r"(a0), "r"(a1), "r"(a2), "r"(a3), "r"(b0), "r"(b1));
}
__device__ __forceinline__ void mma16(float c[4],
    uint32_t a0, uint32_t a1, uint32_t a2, uint32_t a3, uint32_t b0, uint32_t b1) {
    asm volatile(
        "mma.sync.aligned.m16n8k16.row.col.f32.f16.f16.f32 "
        "{%0,%1,%2,%3}, {%4,%5,%6,%7}, {%8,%9}, {%0,%1,%2,%3};\n"
        : "+f"(c[0]), "+f"(c[1]), "+f"(c[2]), "+f"(c[3])
        : "r"(a0), "r"(a1), "r"(a2), "r"(a3), "r"(b0), "r"(b1));
}
__device__ __forceinline__ void cp_commit() { asm volatile("cp.async.commit_group;\n"); }

// ---------------------------------------------------------------------------
// convert: g_T16 = fp16(T), j pair-permuted within each 16-group:
// local pair pl -> position 2*(pl&3) + (pl>>2), so pairs (t, t+4) adjacent.
// ---------------------------------------------------------------------------
__global__ void convert_T16(const float* __restrict__ en) {
    int idx = blockIdx.x * 256 + threadIdx.x;    // pair index, 2^20 total
    float2 v = ((const float2*)en)[idx];
    int p = idx & 63;
    int rowhi = idx >> 6;                        // h*128 + i
    int pl = p & 7, g = p >> 3;
    int pos = g*8 + 2*(pl&3) + (pl>>2);
    uint32_t d;
    asm("cvt.rn.f16x2.f32 %0, %1, %2;" : "=r"(d) : "f"(v.y), "f"(v.x));
    *(uint32_t*)(g_T16 + (size_t)rowhi*128 + pos*2) = d;
}

// ---------------------------------------------------------------------------
// Kernel 1: Z = node2edge @ node_state (tf32). Tile 32 x 128, grid (63,2).
// ---------------------------------------------------------------------------
__global__ __launch_bounds__(256, 2)
void gemm1_kernel(const float* __restrict__ n2e, const float* __restrict__ ns) {
    __shared__ float As[32][36];
    __shared__ float Bs[32][136];
    const int tid = threadIdx.x, lane = tid & 31, warp = tid >> 5;
    const int gid = lane >> 2, tig = lane & 3;
    const int wcol = warp * 16;
    const int b = blockIdx.y, e0 = blockIdx.x * 32;
    const int rows = min(32, EE - e0);
    const float* Ag = n2e + (size_t)b * EE * NN;
    const float* Bg = ns  + (size_t)b * NN * HH;
    float acc[2][2][4] = {};
    const int NC = (NN + 31) / 32;

    float4 ar, br[4];
    auto ldA = [&](int c) {
        int k0 = c * 32, kv = NN - k0;
        int r = tid >> 3, c4 = (tid & 7) * 4;
        ar = make_float4(0.f,0.f,0.f,0.f);
        if (r < rows && c4 < kv) ar = *(const float4*)(Ag + (size_t)(e0 + r) * NN + k0 + c4);
    };
    auto ldB = [&](int c) {
        int k0 = c * 32, kv = NN - k0;
        #pragma unroll
        for (int i = 0; i < 4; i++) {
            int lin = tid + i * 256, kk = lin >> 5, c4 = (lin & 31) * 4;
            br[i] = make_float4(0.f,0.f,0.f,0.f);
            if (kk < kv) br[i] = *(const float4*)(Bg + (size_t)(k0 + kk) * HH + c4);
        }
    };
    ldA(0); ldB(0);

    for (int c = 0; c < NC; c++) {
        __syncthreads();
        { int r = tid >> 3, c4 = (tid & 7) * 4;
          As[r][c4+0]=f2tff(ar.x); As[r][c4+1]=f2tff(ar.y);
          As[r][c4+2]=f2tff(ar.z); As[r][c4+3]=f2tff(ar.w); }
        #pragma unroll
        for (int i = 0; i < 4; i++) {
            int lin = tid + i * 256, kk = lin >> 5, c4 = (lin & 31) * 4;
            Bs[kk][c4+0]=f2tff(br[i].x); Bs[kk][c4+1]=f2tff(br[i].y);
            Bs[kk][c4+2]=f2tff(br[i].z); Bs[kk][c4+3]=f2tff(br[i].w);
        }
        __syncthreads();
        if (c + 1 < NC) { ldA(c + 1); ldB(c + 1); }
        #pragma unroll
        for (int ks = 0; ks < 4; ks++) {
            const int kb = ks * 8;
            uint32_t a[2][4];
            #pragma unroll
            for (int mt = 0; mt < 2; mt++) {
                int r0 = mt * 16 + gid;
                a[mt][0] = __float_as_uint(As[r0    ][kb+tig  ]);
                a[mt][1] = __float_as_uint(As[r0 + 8][kb+tig  ]);
                a[mt][2] = __float_as_uint(As[r0    ][kb+tig+4]);
                a[mt][3] = __float_as_uint(As[r0 + 8][kb+tig+4]);
            }
            #pragma unroll
            for (int nt = 0; nt < 2; nt++) {
                int colb = wcol + nt * 8 + gid;
                uint32_t b0 = __float_as_uint(Bs[kb+tig  ][colb]);
                uint32_t b1 = __float_as_uint(Bs[kb+tig+4][colb]);
                mma8(acc[0][nt], a[0][0],a[0][1],a[0][2],a[0][3], b0,b1);
                mma8(acc[1][nt], a[1][0],a[1][1],a[1][2],a[1][3], b0,b1);
            }
        }
    }
    #pragma unroll
    for (int mt = 0; mt < 2; mt++)
        #pragma unroll
        for (int nt = 0; nt < 2; nt++) {
            int col = wcol + nt * 8 + tig * 2;
            int r0 = mt * 16 + gid, r1 = r0 + 8;
            if (r0 < rows) { float* p = g_Z + ((size_t)(b*EE + e0 + r0))*HH + col; p[0]=acc[mt][nt][0]; p[1]=acc[mt][nt][1]; }
            if (r1 < rows) { float* p = g_Z + ((size_t)(b*EE + e0 + r1))*HH + col; p[0]=acc[mt][nt][2]; p[1]=acc[mt][nt][3]; }
        }
}

// ---------------------------------------------------------------------------
// MAIN (fp16 m16n8k16): Y[r,i] = sum_{h,j} X[r,h]*T[h,i,j]*Z[r,j].
// 512 thr, tile 128 r x 128 i; split-K over h (4 x 32); grid (32,4)=128 CTAs.
// K=128 per iteration (one full h): 32 iterations total.
// P (=x*z fp16, full 128x128) double-buffered, built cooperatively;
// T_h (fp16, pair-permuted) 3-deep cp.async ring. 288B row stride
// (conflict-free frag LDS.64). All frag loads VOLATILE (ordering).
// ---------------------------------------------------------------------------
#define TB_BYTES 36864                      // 128 rows * 288B
#define PB_OFF   (3*TB_BYTES)               // 110592
#define PB_BYTES 36864
#define XS_OFF   (PB_OFF + 2*PB_BYTES)      // 184320
#define MAIN_SMEM (XS_OFF + 128*36*4)       // 202752 B

__global__ __launch_bounds__(512, 1)
void gemm_main_kernel(const float* __restrict__ ev) {
    extern __shared__ char smc[];
    uint32_t sb;
    asm("{ .reg .u64 t; cvta.to.shared.u64 t, %1; cvt.u32.u64 %0, t; }" : "=r"(sb) : "l"((void*)smc));
    float* Xs = (float*)(smc + XS_OFF);
    const int tid = threadIdx.x, lane = tid & 31, warp = tid >> 5;
    const int gid = lane >> 2, tig = lane & 3;
    const int wrow = (warp & 3) * 32, wcol = (warp >> 2) * 32;
    const int row0 = blockIdx.x * 128;
    const int h0 = blockIdx.y * 32;

    // T_h copy: 32KB per chunk, 4 x 16B per thread (rows contiguous in gmem)
    auto issueT = [&](int c) {
        const unsigned short* srcb = g_T16 + ((size_t)(h0 + c) * 128) * 128;
        uint32_t dstb = sb + (uint32_t)(c % 3) * TB_BYTES;
        #pragma unroll
        for (int k2 = 0; k2 < 4; k2++) {
            int lin = tid + k2 * 512;
            int r = lin >> 4, seg = lin & 15;
            asm volatile("cp.async.cg.shared.global [%0], [%1], 16;\n"
                         :: "r"(dstb + r*288 + seg*16), "l"(srcb + r*128 + seg*8));
        }
    };
    issueT(0); cp_commit();
    issueT(1); cp_commit();

    // Xs[r][h] fp32, stride 36 (guarded: rows >= BE -> 0)
    #pragma unroll
    for (int i = 0; i < 2; i++) {
        int lin = tid + i * 512, r = lin >> 3, c4 = (lin & 7) * 4;
        float4 v = make_float4(0.f,0.f,0.f,0.f);
        if (row0 + r < BE) v = *(const float4*)(ev + (size_t)(row0 + r) * HH + h0 + c4);
        Xs[r*36+c4]=v.x; Xs[r*36+c4+1]=v.y; Xs[r*36+c4+2]=v.z; Xs[r*36+c4+3]=v.w;
    }

    // builder: thread -> (row, quarter); 32 z values in regs, loaded once.
    // quarter bq covers positions [bq*16, bq*16+16) pairs = 4 sub-quarters.
    const int brow = tid >> 2, bq = tid & 3;
    const uint32_t bdst = sb + PB_OFF + brow * 288 + bq * 64;
    const float* zrow = g_Z + (size_t)(row0 + brow) * HH;   // padded, no guard
    float zv[32];
    #pragma unroll
    for (int s = 0; s < 4; s++) {
        int q = bq * 4 + s;                 // global sub-quarter 0..15
        int b1 = (q >> 1) * 16 + (q & 1) * 4;
        float4 u = *(const float4*)(zrow + b1);
        float4 w = *(const float4*)(zrow + b1 + 8);
        zv[s*8+0]=u.x; zv[s*8+1]=u.y; zv[s*8+2]=u.z; zv[s*8+3]=u.w;
        zv[s*8+4]=w.x; zv[s*8+5]=w.y; zv[s*8+6]=w.z; zv[s*8+7]=w.w;
    }
    auto buildP = [&](int nc) {
        float x = Xs[brow*36 + nc];
        uint32_t d = bdst + (uint32_t)(nc & 1) * PB_BYTES;
        #pragma unroll
        for (int s = 0; s < 4; s++) {
            uint32_t r0,r1,r2,r3;
            asm("cvt.rn.f16x2.f32 %0, %1, %2;" : "=r"(r0) : "f"(x*zv[s*8+1]), "f"(x*zv[s*8+0]));
            asm("cvt.rn.f16x2.f32 %0, %1, %2;" : "=r"(r1) : "f"(x*zv[s*8+5]), "f"(x*zv[s*8+4]));
            asm("cvt.rn.f16x2.f32 %0, %1, %2;" : "=r"(r2) : "f"(x*zv[s*8+3]), "f"(x*zv[s*8+2]));
            asm("cvt.rn.f16x2.f32 %0, %1, %2;" : "=r"(r3) : "f"(x*zv[s*8+7]), "f"(x*zv[s*8+6]));
            asm volatile("st.shared.v4.b32 [%0], {%1,%2,%3,%4};"
                         :: "r"(d + s*16), "r"(r0), "r"(r1), "r"(r2), "r"(r3));
        }
    };
    __syncthreads();     // Xs visible
    buildP(0);

    float acc[2][4][4] = {};

    for (int cc = 0; cc < 32; cc++) {
        asm volatile("cp.async.wait_group 1;\n" ::: "memory");
        __syncthreads();                 // P(cc) + T(cc) visible; prev reads done
        if (cc + 2 < 32) issueT(cc + 2);
        cp_commit();
        if (cc + 1 < 32) buildP(cc + 1);
        uint32_t Pbuf = sb + PB_OFF + (uint32_t)(cc & 1) * PB_BYTES;
        uint32_t Tbuf = sb + (uint32_t)(cc % 3) * TB_BYTES;
        #pragma unroll
        for (int ks = 0; ks < 8; ks++) {
            uint32_t a0[2], a1[2], a2[2], a3[2];
            #pragma unroll
            for (int mt = 0; mt < 2; mt++) {
                uint32_t ra = Pbuf + (uint32_t)(wrow + mt*16 + gid) * 288 + ks*32 + tig*8;
                asm volatile("ld.shared.v2.b32 {%0,%1}, [%2];"
                             : "=r"(a0[mt]), "=r"(a2[mt]) : "r"(ra) : "memory");
                asm volatile("ld.shared.v2.b32 {%0,%1}, [%2];"
                             : "=r"(a1[mt]), "=r"(a3[mt]) : "r"(ra + 8*288) : "memory");
            }
            #pragma unroll
            for (int nt = 0; nt < 4; nt++) {
                uint32_t rb = Tbuf + (uint32_t)(wcol + nt*8 + gid) * 288 + ks*32 + tig*8;
                uint32_t b0, b1;
                asm volatile("ld.shared.v2.b32 {%0,%1}, [%2];"
                             : "=r"(b0), "=r"(b1) : "r"(rb) : "memory");
                mma16(acc[0][nt], a0[0],a1[0],a2[0],a3[0], b0,b1);
                mma16(acc[1][nt], a0[1],a1[1],a2[1],a3[1], b0,b1);
            }
        }
    }

    // padded g_Ypart -> no row guard
    float* Yp = g_Ypart[blockIdx.y];
    #pragma unroll
    for (int mt = 0; mt < 2; mt++)
        #pragma unroll
        for (int nt = 0; nt < 4; nt++) {
            int col = wcol + nt * 8 + tig * 2;
            int r0 = row0 + wrow + mt * 16 + gid;
            float* p0 = Yp + (size_t)r0 * HH + col;
            p0[0] = acc[mt][nt][0]; p0[1] = acc[mt][nt][1];
            float* p1 = Yp + (size_t)(r0 + 8) * HH + col;
            p1[0] = acc[mt][nt][2]; p1[1] = acc[mt][nt][3];
        }
}

// ---------------------------------------------------------------------------
__global__ void reduce_kernel() {
    int i0 = (blockIdx.x * 256 + threadIdx.x) * 8;
    #pragma unroll
    for (int half = 0; half < 2; half++) {
        int idx = i0 + half * 4;
        float4 a = *(const float4*)&g_Ypart[0][idx];
        float4 b = *(const float4*)&g_Ypart[1][idx];
        float4 c = *(const float4*)&g_Ypart[2][idx];
        float4 d = *(const float4*)&g_Ypart[3][idx];
        *(float4*)&g_Y[idx] = make_float4(a.x+b.x+c.x+d.x, a.y+b.y+c.y+d.y,
                                          a.z+b.z+c.z+d.z, a.w+b.w+c.w+d.w);
    }
}

// ---------------------------------------------------------------------------
// Kernel 3: out = (edge2node @ Y + node_state) / (1 + rowsum(edge2node)).
// Tile 16 x 128, norm fused into A loads. grid (63, 2).
// ---------------------------------------------------------------------------
__global__ __launch_bounds__(256, 2)
void gemm3_kernel(const float* __restrict__ e2n, const float* __restrict__ ns,
                  float* __restrict__ out) {
    __shared__ float As[16][36];
    __shared__ float Bs[32][136];
    __shared__ float nsp[128];
    __shared__ float nv_s[16];
    const int tid = threadIdx.x, lane = tid & 31, warp = tid >> 5;
    const int gid = lane >> 2, tig = lane & 3;
    const int wcol = warp * 16;
    const int b = blockIdx.y, n0 = blockIdx.x * 16;
    const int rows = min(16, NN - n0);
    const float* Ag = e2n + ((size_t)b * NN + n0) * EE;
    const float* Bg = g_Y + (size_t)b * EE * HH;
    float acc[2][4] = {};
    float asum = 0.f;
    const int NC = (EE + 31) / 32;

    float4 ar, br[4];
    auto ldA = [&](int c) {
        int k0 = c * 32, kv = EE - k0;
        int r = tid >> 3, c4 = (tid & 7) * 4;
        ar = make_float4(0.f,0.f,0.f,0.f);
        if (r < rows && c4 < kv && tid < 128)
            ar = *(const float4*)(Ag + (size_t)r * EE + k0 + c4);
        asum += ar.x + ar.y + ar.z + ar.w;
    };
    auto ldB = [&](int c) {
        int k0 = c * 32, kv = EE - k0;
        #pragma unroll
        for (int i = 0; i < 4; i++) {
            int lin = tid + i * 256, kk = lin >> 5, c4 = (lin & 31) * 4;
            br[i] = make_float4(0.f,0.f,0.f,0.f);
            if (kk < kv) br[i] = *(const float4*)(Bg + (size_t)(k0 + kk) * HH + c4);
        }
    };
    ldA(0); ldB(0);

    for (int c = 0; c < NC; c++) {
        __syncthreads();
        if (tid < 128) {
            int r = tid >> 3, c4 = (tid & 7) * 4;
            As[r][c4+0]=f2tff(ar.x); As[r][c4+1]=f2tff(ar.y);
            As[r][c4+2]=f2tff(ar.z); As[r][c4+3]=f2tff(ar.w);
        }
        #pragma unroll
        for (int i = 0; i < 4; i++) {
            int lin = tid + i * 256, kk = lin >> 5, c4 = (lin & 31) * 4;
            Bs[kk][c4+0]=f2tff(br[i].x); Bs[kk][c4+1]=f2tff(br[i].y);
            Bs[kk][c4+2]=f2tff(br[i].z); Bs[kk][c4+3]=f2tff(br[i].w);
        }
        __syncthreads();
        if (c + 1 < NC) { ldA(c + 1); ldB(c + 1); }
        #pragma unroll
        for (int ks = 0; ks < 4; ks++) {
            const int kb = ks * 8;
            uint32_t a0 = __float_as_uint(As[gid    ][kb+tig  ]);
            uint32_t a1 = __float_as_uint(As[gid + 8][kb+tig  ]);
            uint32_t a2 = __float_as_uint(As[gid    ][kb+tig+4]);
            uint32_t a3 = __float_as_uint(As[gid + 8][kb+tig+4]);
            #pragma unroll
            for (int nt = 0; nt < 2; nt++) {
                int colb = wcol + nt * 8 + gid;
                uint32_t b0 = __float_as_uint(Bs[kb+tig  ][colb]);
                uint32_t b1 = __float_as_uint(Bs[kb+tig+4][colb]);
                mma8(acc[nt], a0, a1, a2, a3, b0, b1);
            }
        }
    }
    if (tid < 128) nsp[tid] = asum;
    __syncthreads();
    if (tid < 16) {
        float s = 1.f;
        #pragma unroll
        for (int k = 0; k < 8; k++) s += nsp[tid*8 + k];
        nv_s[tid] = s;
    }
    __syncthreads();

    const float* nsb = ns + ((size_t)b * NN) * HH;
    #pragma unroll
    for (int nt = 0; nt < 2; nt++) {
        int col = wcol + nt * 8 + tig * 2;
        int r0 = gid, r1 = gid + 8;
        if (r0 < rows) {
            size_t idx = (size_t)(n0 + r0) * HH + col;
            float nv = nv_s[r0];
            float* po = out + (size_t)b * NN * HH + idx;
            po[0] = (acc[nt][0] + nsb[idx  ]) / nv;
            po[1] = (acc[nt][1] + nsb[idx+1]) / nv;
        }
        if (r1 < rows) {
            size_t idx = (size_t)(n0 + r1) * HH + col;
            float nv = nv_s[r1];
            float* po = out + (size_t)b * NN * HH + idx;
            po[0] = (acc[nt][2] + nsb[idx  ]) / nv;
            po[1] = (acc[nt][3] + nsb[idx+1]) / nv;
        }
    }
}

// ---------------------------------------------------------------------------
extern "C" void kernel_launch(void* const* d_in, const int* in_sizes, int n_in,
                              void* d_out, int out_size) {
    const float* node_state = (const float*)d_in[0];
    const float* edge_vec   = (const float*)d_in[1];
    const float* node2edge  = (const float*)d_in[2];
    const float* edge2node  = (const float*)d_in[3];
    const float* edge_net   = (const float*)d_in[4];
    float* out = (float*)d_out;

    cudaFuncSetAttribute(gemm_main_kernel,
                         cudaFuncAttributeMaxDynamicSharedMemorySize, MAIN_SMEM);

    convert_T16<<<4096, 256>>>(edge_net);
    gemm1_kernel<<<dim3(63, 2), 256>>>(node2edge, node_state);
    gemm_main_kernel<<<dim3(32, SPLITK), 512, MAIN_SMEM>>>(edge_vec);
    reduce_kernel<<<250, 256>>>();
    gemm3_kernel<<<dim3(63, 2), 256>>>(edge2node, node_state, out);
}